// round 3
// baseline (speedup 1.0000x reference)
#include <cuda_runtime.h>
#include <math_constants.h>

#define NPTS 256
#define NBATCH 8
#define FULLMASK 0xffffffffu

// Per-batch matched-cost sums (no device allocation allowed).
__device__ float g_batch_sum[NBATCH];

// Order-preserving float <-> uint maps (REDUX.MIN on float keys).
__device__ __forceinline__ unsigned ford(float f) {
    unsigned u = __float_as_uint(f);
    return (u & 0x80000000u) ? ~u : (u | 0x80000000u);
}
__device__ __forceinline__ float funord(unsigned x) {
    unsigned u = (x & 0x80000000u) ? (x & 0x7fffffffu) : ~x;
    return __uint_as_float(u);
}

// One CTA per batch. Full Jonker-Volgenant:
//   1) column reduction + greedy init (parallel, deterministic)
//   2) augmenting row reduction (ARR), 2 rounds, iteration-capped
//   3) shortest-augmenting-path for the remaining free rows
__global__ __launch_bounds__(NPTS) void emd_lsa_kernel(
    const float* __restrict__ pred, const float* __restrict__ label) {
    const int b = blockIdx.x;
    const int tid = threadIdx.x;
    const int lane = tid & 31;
    const int warp = tid >> 5;

    __shared__ float px[NPTS], py[NPTS], pz[NPTS];
    __shared__ float sx[NPTS], sy[NPTS], sz[NPTS];
    __shared__ float u_s[NPTS], v_s[NPTS], shortest_s[NPTS];
    __shared__ int row4col_s[NPTS], col4row_s[NPTS], path_s[NPTS];
    __shared__ int rowclaim[NPTS];
    __shared__ unsigned long long wslot[2][8];
    __shared__ int flist[2][NPTS];
    __shared__ int s_i, s_active;

    // ---- load coords ----
    const float* P = pred + (size_t)b * NPTS * 3;
    const float* L = label + (size_t)b * NPTS * 3;
    px[tid] = P[tid * 3 + 0];
    py[tid] = P[tid * 3 + 1];
    pz[tid] = P[tid * 3 + 2];
    sx[tid] = L[tid * 3 + 0];
    sy[tid] = L[tid * 3 + 1];
    sz[tid] = L[tid * 3 + 2];
    row4col_s[tid] = -1;
    col4row_s[tid] = -1;
    u_s[tid] = 0.0f;
    rowclaim[tid] = 0x7fffffff;
    __syncthreads();

    // own-column label coords in registers
    const float lxr = sx[tid], lyr = sy[tid], lzr = sz[tid];

    // ---- phase 1: column reduction v[j]=min_i c(i,j) + greedy claim ----
    {
        float vmin = CUDART_INF_F;
        int varg = 0;
        for (int i = 0; i < NPTS; ++i) {
            float dx = px[i] - lxr, dy = py[i] - lyr, dz = pz[i] - lzr;
            float c = sqrtf(fmaf(dx, dx, fmaf(dy, dy, dz * dz)));
            if (c < vmin) { vmin = c; varg = i; }
        }
        v_s[tid] = vmin;
        atomicMin(&rowclaim[varg], tid);  // min-col claim: deterministic
    }
    __syncthreads();
    {
        int c = rowclaim[tid];  // tid = row here
        if (c != 0x7fffffff) { col4row_s[tid] = c; row4col_s[c] = tid; }
    }
    __syncthreads();

    // ---- phase 2: augmenting row reduction (2 rounds, capped) ----
    {
        // thread-0 private list state persists in registers across iterations
        int head = 0, nf = 0, nf_next = 0, round = 0, iters = 0;
        if (tid == 0) {
            for (int i2 = 0; i2 < NPTS; ++i2)
                if (col4row_s[i2] < 0) flist[0][nf++] = i2;
            if (nf > 0) { s_i = flist[0][head++]; s_active = 1; }
            else s_active = 0;
        }
        __syncthreads();

        while (true) {
            if (!s_active) break;
            const int i = s_i;
            // reduced cost of column tid vs row i
            float dx = px[i] - lxr, dy = py[i] - lyr, dz = pz[i] - lzr;
            float c = sqrtf(fmaf(dx, dx, fmaf(dy, dy, dz * dz)));
            float r = c - v_s[tid];
            unsigned key = ford(r);
            unsigned m1 = __reduce_min_sync(FULLMASK, key);
            int l1 = __ffs(__ballot_sync(FULLMASK, key == m1)) - 1;
            unsigned key2 = (lane == l1) ? 0xffffffffu : key;
            unsigned m2 = __reduce_min_sync(FULLMASK, key2);
            int l2 = __ffs(__ballot_sync(FULLMASK, key2 == m2)) - 1;
            if (lane == l1)
                wslot[0][warp] = ((unsigned long long)m1 << 32) | (unsigned)(warp * 32 + l1);
            if (lane == l2)
                wslot[1][warp] = ((unsigned long long)m2 << 32) | (unsigned)(warp * 32 + l2);
            __syncthreads();

            if (tid == 0) {
                unsigned long long bestA = wslot[0][0];
                int wA = 0;
#pragma unroll
                for (int w = 1; w < 8; ++w)
                    if (wslot[0][w] < bestA) { bestA = wslot[0][w]; wA = w; }
                unsigned long long second = wslot[1][wA];
#pragma unroll
                for (int w = 0; w < 8; ++w)
                    if (w != wA && wslot[0][w] < second) second = wslot[0][w];
                unsigned m1b = (unsigned)(bestA >> 32);
                unsigned m2b = (unsigned)(second >> 32);
                int j1 = (int)(bestA & 0xffffffffull);
                int j2 = (int)(second & 0xffffffffull);
                float u1 = funord(m1b), u2 = funord(m2b);
                u_s[i] = u2;
                bool strict = (m1b < m2b);
                if (strict) v_s[j1] -= (u2 - u1);
                else if (row4col_s[j1] >= 0) j1 = j2;
                int k = row4col_s[j1];
                row4col_s[j1] = i;
                col4row_s[i] = j1;
                int nexti = -1;
                if (k >= 0) {
                    col4row_s[k] = -1;
                    if (strict) nexti = k;                 // chase displaced row
                    else flist[round ^ 1][nf_next++] = k;  // tie: defer a round
                }
                if (nexti < 0) {
                    while (true) {
                        if (head < nf) { nexti = flist[round][head++]; break; }
                        if (round == 0 && nf_next > 0) {
                            round = 1; nf = nf_next; nf_next = 0; head = 0;
                            continue;
                        }
                        break;
                    }
                }
                if (++iters > 2048 || nexti < 0) s_active = 0;
                else s_i = nexti;
            }
            __syncthreads();
        }
    }

    // reload duals into registers for the SAP phase
    float u_reg = u_s[tid];
    float v_reg = v_s[tid];

    // ---- phase 3: shortest augmenting paths for remaining free rows ----
    for (int cur = 0; cur < NPTS; ++cur) {
        if (col4row_s[cur] >= 0) continue;

        float shortest_reg = CUDART_INF_F;
        int path_reg = 0;
        bool SC_reg = false;
        bool SR_reg = (tid == cur);
        int i = cur;
        float mv = 0.0f;
        int parity = 0;
        int sink = -1;

        while (true) {
            const float u_i = u_s[i];
            float dx = px[i] - lxr, dy = py[i] - lyr, dz = pz[i] - lzr;
            float c = sqrtf(fmaf(dx, dx, fmaf(dy, dy, dz * dz)));
            float r = mv + c - u_i - v_reg;
            if (!SC_reg && r < shortest_reg) { shortest_reg = r; path_reg = i; }

            unsigned key = SC_reg ? 0xffffffffu : ford(shortest_reg);
            unsigned m = __reduce_min_sync(FULLMASK, key);
            unsigned ball = __ballot_sync(FULLMASK, key == m);
            if (lane == __ffs(ball) - 1)
                wslot[parity][warp] = ((unsigned long long)m << 32) | (unsigned)tid;
            __syncthreads();

            unsigned long long best = wslot[parity][0];
#pragma unroll
            for (int w = 1; w < 8; ++w) {
                unsigned long long x = wslot[parity][w];
                if (x < best) best = x;
            }
            parity ^= 1;

            int bj = (int)(unsigned)best;
            mv = funord((unsigned)(best >> 32));
            if (tid == bj) SC_reg = true;

            int r4 = row4col_s[bj];
            if (r4 < 0) { sink = bj; break; }
            i = r4;
            if (tid == i) SR_reg = true;
        }

        shortest_s[tid] = shortest_reg;
        path_s[tid] = path_reg;
        __syncthreads();

        // dual update (reads OLD col4row, before augment)
        if (tid == cur) {
            u_reg += mv;
        } else if (SR_reg) {
            u_reg += mv - shortest_s[col4row_s[tid]];
        }
        if (SR_reg) u_s[tid] = u_reg;
        if (SC_reg) v_reg -= mv - shortest_reg;
        __syncthreads();

        if (tid == 0) {
            int j = sink;
            while (true) {
                int ii = path_s[j];
                row4col_s[j] = ii;
                int nj = col4row_s[ii];
                col4row_s[ii] = j;
                j = nj;
                if (ii == cur) break;
            }
        }
        __syncthreads();
    }

    // ---- matched distance per row, exact recompute ----
    {
        int j = col4row_s[tid];
        float dx = px[tid] - sx[j];
        float dy = py[tid] - sy[j];
        float dz = pz[tid] - sz[j];
        shortest_s[tid] = sqrtf(fmaf(dx, dx, fmaf(dy, dy, dz * dz)));
    }
    __syncthreads();
#pragma unroll
    for (int s = 128; s > 0; s >>= 1) {
        if (tid < s) shortest_s[tid] += shortest_s[tid + s];
        __syncthreads();
    }
    if (tid == 0) g_batch_sum[b] = shortest_s[0];
}

// Deterministic fixed-order final reduction.
__global__ void emd_reduce_kernel(float* __restrict__ out) {
    float s = 0.0f;
#pragma unroll
    for (int bb = 0; bb < NBATCH; ++bb) s += g_batch_sum[bb];
    out[0] = s / (float)(NBATCH * NPTS);
}

extern "C" void kernel_launch(void* const* d_in, const int* in_sizes, int n_in,
                              void* d_out, int out_size) {
    const float* pred = (const float*)d_in[0];
    const float* label = (const float*)d_in[1];
    float* out = (float*)d_out;
    emd_lsa_kernel<<<NBATCH, NPTS>>>(pred, label);
    emd_reduce_kernel<<<1, 1>>>(out);
}

// round 4
// speedup vs baseline: 2.1170x; 2.1170x over previous
#include <cuda_runtime.h>
#include <math_constants.h>

#define NPTS 256
#define NT 128      // threads per CTA
#define NC 2        // columns (and rows) owned per thread
#define NBATCH 8
#define FULLMASK 0xffffffffu

// Per-batch matched-cost sums (no device allocation allowed).
__device__ float g_batch_sum[NBATCH];

// Order-preserving float -> uint map (REDUX.MIN on float keys).
__device__ __forceinline__ unsigned ford(float f) {
    unsigned u = __float_as_uint(f);
    return (u & 0x80000000u) ? ~u : (u | 0x80000000u);
}
// Single-MUFU sqrt for the search phases (final loss uses IEEE sqrtf).
__device__ __forceinline__ float fsqrt_fast(float x) {
    float r;
    asm("sqrt.approx.f32 %0, %1;" : "=f"(r) : "f"(x));
    return r;
}

// One CTA per batch. JV: column reduction + greedy init, then shortest
// augmenting paths. Thread t owns cols {t, t+128} and rows {t, t+128}.
__global__ __launch_bounds__(NT) void emd_lsa_kernel(
    const float* __restrict__ pred, const float* __restrict__ label) {
    const int b = blockIdx.x;
    const int tid = threadIdx.x;
    const int warp = tid >> 5;

    __shared__ float px[NPTS], py[NPTS], pz[NPTS];
    __shared__ float sx[NPTS], sy[NPTS], sz[NPTS];
    __shared__ float u_s[NPTS], shortest_s[NPTS];
    __shared__ int row4col_s[NPTS], col4row_s[NPTS], path_s[NPTS];
    __shared__ int rowclaim[NPTS];
    __shared__ __align__(16) unsigned wslot[2][4];  // double-buffered warp keys

    // ---- load coords + init state ----
    const float* P = pred + (size_t)b * NPTS * 3;
    const float* L = label + (size_t)b * NPTS * 3;
#pragma unroll
    for (int k = 0; k < NC; ++k) {
        int j = tid + NT * k;
        px[j] = P[j * 3 + 0];
        py[j] = P[j * 3 + 1];
        pz[j] = P[j * 3 + 2];
        sx[j] = L[j * 3 + 0];
        sy[j] = L[j * 3 + 1];
        sz[j] = L[j * 3 + 2];
        row4col_s[j] = -1;
        col4row_s[j] = -1;
        u_s[j] = 0.0f;
        rowclaim[j] = 0x7fffffff;
    }
    __syncthreads();

    // own-column label coords in registers
    float lx[NC], ly[NC], lz[NC], v[NC];
#pragma unroll
    for (int k = 0; k < NC; ++k) {
        int j = tid + NT * k;
        lx[k] = sx[j];
        ly[k] = sy[j];
        lz[k] = sz[j];
    }

    // ---- phase 1: column reduction v[j]=min_i c(i,j) + greedy claim ----
#pragma unroll
    for (int k = 0; k < NC; ++k) {
        float vmin = CUDART_INF_F;
        int varg = 0;
        for (int i = 0; i < NPTS; ++i) {
            float dx = px[i] - lx[k], dy = py[i] - ly[k], dz = pz[i] - lz[k];
            float c = fsqrt_fast(fmaf(dx, dx, fmaf(dy, dy, dz * dz)));
            if (c < vmin) { vmin = c; varg = i; }
        }
        v[k] = vmin;
        atomicMin(&rowclaim[varg], tid + NT * k);  // min-col claim: deterministic
    }
    __syncthreads();
#pragma unroll
    for (int k = 0; k < NC; ++k) {
        int r = tid + NT * k;
        int c = rowclaim[r];
        if (c != 0x7fffffff) { col4row_s[r] = c; row4col_s[c] = r; }
    }
    __syncthreads();

    // ---- phase 2: shortest augmenting paths for free rows ----
    for (int cur = 0; cur < NPTS; ++cur) {
        if (col4row_s[cur] >= 0) continue;  // uniform smem read

        float shortest[NC];
        int path[NC];
        bool SC[NC], SR[NC];
#pragma unroll
        for (int k = 0; k < NC; ++k) {
            shortest[k] = CUDART_INF_F;
            path[k] = 0;
            SC[k] = false;
            SR[k] = ((tid + NT * k) == cur);
        }
        int i = cur;
        float mv = 0.0f;
        int parity = 0;
        int sink = -1;

        while (true) {
            const float ui = u_s[i];
            const float pix = px[i], piy = py[i], piz = pz[i];
            unsigned lkey = 0xffffffffu;
#pragma unroll
            for (int k = 0; k < NC; ++k) {
                const unsigned col = (unsigned)(tid + NT * k);
                unsigned key;
                if (!SC[k]) {
                    float dx = pix - lx[k], dy = piy - ly[k], dz = piz - lz[k];
                    float c = fsqrt_fast(fmaf(dx, dx, fmaf(dy, dy, dz * dz)));
                    float r = mv + c - ui - v[k];
                    if (r < shortest[k]) { shortest[k] = r; path[k] = i; }
                    key = (ford(shortest[k]) & 0xffffff00u) | col;
                } else {
                    key = 0xffffff00u | col;  // scanned: worse than any live key
                }
                shortest_s[col] = shortest[k];  // publish exact value
                lkey = min(lkey, key);
            }
            // warp min; key uniqueness (col in low bits) -> single writer
            unsigned m = __reduce_min_sync(FULLMASK, lkey);
            if (lkey == m) wslot[parity][warp] = m;
            __syncthreads();

            uint4 ws = *(const uint4*)&wslot[parity][0];
            unsigned best = min(min(ws.x, ws.y), min(ws.z, ws.w));
            parity ^= 1;

            const int bj = (int)(best & 0xffu);
            mv = shortest_s[bj];              // exact value of selected column
            const int r4 = row4col_s[bj];
            if (tid == (bj & (NT - 1))) SC[bj >> 7] = true;
            if (r4 < 0) { sink = bj; break; }
            i = r4;
            if (tid == (i & (NT - 1))) SR[i >> 7] = true;
        }

        // publish path for the augment walk
#pragma unroll
        for (int k = 0; k < NC; ++k) path_s[tid + NT * k] = path[k];
        __syncthreads();

        // dual updates (read OLD col4row, before augment)
#pragma unroll
        for (int k = 0; k < NC; ++k) {
            int r = tid + NT * k;
            if (SR[k]) {
                if (r == cur) u_s[r] += mv;
                else u_s[r] += mv - shortest_s[col4row_s[r]];
            }
            if (SC[k]) v[k] -= mv - shortest[k];
        }
        __syncthreads();

        // augment along alternating path (short serial walk)
        if (tid == 0) {
            int j = sink;
            while (true) {
                int ii = path_s[j];
                row4col_s[j] = ii;
                int nj = col4row_s[ii];
                col4row_s[ii] = j;
                j = nj;
                if (ii == cur) break;
            }
        }
        __syncthreads();
    }

    // ---- matched distance per row, exact IEEE recompute ----
#pragma unroll
    for (int k = 0; k < NC; ++k) {
        int r = tid + NT * k;
        int j = col4row_s[r];
        float dx = px[r] - sx[j];
        float dy = py[r] - sy[j];
        float dz = pz[r] - sz[j];
        shortest_s[r] = sqrtf(fmaf(dx, dx, fmaf(dy, dy, dz * dz)));
    }
    __syncthreads();
#pragma unroll
    for (int s = 128; s > 0; s >>= 1) {
        if (tid < s) shortest_s[tid] += shortest_s[tid + s];
        __syncthreads();
    }
    if (tid == 0) g_batch_sum[b] = shortest_s[0];
}

// Deterministic fixed-order final reduction.
__global__ void emd_reduce_kernel(float* __restrict__ out) {
    float s = 0.0f;
#pragma unroll
    for (int bb = 0; bb < NBATCH; ++bb) s += g_batch_sum[bb];
    out[0] = s / (float)(NBATCH * NPTS);
}

extern "C" void kernel_launch(void* const* d_in, const int* in_sizes, int n_in,
                              void* d_out, int out_size) {
    const float* pred = (const float*)d_in[0];
    const float* label = (const float*)d_in[1];
    float* out = (float*)d_out;
    emd_lsa_kernel<<<NBATCH, NT>>>(pred, label);
    emd_reduce_kernel<<<1, 1>>>(out);
}